// round 2
// baseline (speedup 1.0000x reference)
#include <cuda_runtime.h>
#include <cuda_bf16.h>
#include <math.h>

// Problem constants (fixed by the dataset)
#define N_SPOTS   100000
#define N_GENES   512
#define N_SPH     511          // N_GENES - 1
#define N_EDGES   600000
#define N_NEI     6

// ---------------- scratch (device globals: no allocation allowed) ----------
__device__ float g_gex[(size_t)N_SPOTS * N_GENES];   // 204.8 MB
__device__ float g_x  [(size_t)N_SPOTS * N_GENES];   // 204.8 MB  (gex @ Wc^T)
__device__ float g_deg [N_SPOTS];
__device__ float g_dinv[N_SPOTS];
__device__ float g_colsum[N_GENES];

// ---------------- init: zero deg + colsum ----------------------------------
__global__ void k_zero(void) {
    int i = blockIdx.x * blockDim.x + threadIdx.x;
    if (i < N_SPOTS) g_deg[i] = 0.0f;
    if (i < N_GENES) g_colsum[i] = 0.0f;
}

// ---------------- gex: warp-per-row product scan ----------------------------
// gex[n,i] = (prod_{j<i} sin(sphex[n,j])) * cos(sphex[n,i])  for i < 511
// gex[n,511] = prod_{j<511} sin(sphex[n,j])
__global__ void k_gex(const float* __restrict__ sphex) {
    int gwarp = (blockIdx.x * blockDim.x + threadIdx.x) >> 5;
    int lane  = threadIdx.x & 31;
    if (gwarp >= N_SPOTS) return;
    const float* row = sphex + (size_t)gwarp * N_SPH;
    float* orow = g_gex + (size_t)gwarp * N_GENES;

    float P = 1.0f;  // running product of sins of previous chunks
    for (int base = 0; base < N_SPH; base += 32) {
        int idx = base + lane;
        float s = 1.0f, c = 1.0f;
        if (idx < N_SPH) {
            float xv = row[idx];
            sincosf(xv, &s, &c);
        }
        // inclusive product scan across the warp
        float incl = s;
        #pragma unroll
        for (int off = 1; off < 32; off <<= 1) {
            float o = __shfl_up_sync(0xffffffffu, incl, off);
            if (lane >= off) incl *= o;
        }
        float excl = __shfl_up_sync(0xffffffffu, incl, 1);
        if (lane == 0) excl = 1.0f;
        if (idx < N_SPH) orow[idx] = P * excl * c;
        P *= __shfl_sync(0xffffffffu, incl, 31);
    }
    if (lane == 0) orow[N_SPH] = P;   // last gene = full cumprod of sins
}

// ---------------- SGEMM: C[m,o] = sum_k A[m,k] * W[o,k] (+ bias[o]) --------
// A: M x 512 row-major, W: 512 x 512 row-major. Tile 128x128x8, 256 threads,
// 8x8 per-thread microtile.
template <bool ADD_BIAS>
__global__ void __launch_bounds__(256, 2)
k_sgemm512(const float* __restrict__ A, const float* __restrict__ W,
           const float* __restrict__ bias, float* __restrict__ C, int M) {
    const int K = N_GENES;
    __shared__ float As[8][128];
    __shared__ float Bs[8][128];

    int tid = threadIdx.x;
    int n0 = blockIdx.x * 128;
    int m0 = blockIdx.y * 128;

    int ar = tid >> 1;            // 0..127 (tile row for loads)
    int ac = (tid & 1) * 4;       // 0 or 4 (k offset)
    int ty = tid >> 4;            // 0..15
    int tx = tid & 15;            // 0..15

    bool arow_ok = (m0 + ar) < M;
    const float* Aptr = A + (size_t)(m0 + ar) * K + ac;
    const float* Wptr = W + (size_t)(n0 + ar) * K + ac;

    float acc[8][8];
    #pragma unroll
    for (int i = 0; i < 8; i++)
        #pragma unroll
        for (int j = 0; j < 8; j++) acc[i][j] = 0.0f;

    for (int kt = 0; kt < K; kt += 8) {
        float4 av = arow_ok ? *(const float4*)(Aptr + kt) : make_float4(0.f,0.f,0.f,0.f);
        float4 wv = *(const float4*)(Wptr + kt);
        As[ac + 0][ar] = av.x; As[ac + 1][ar] = av.y;
        As[ac + 2][ar] = av.z; As[ac + 3][ar] = av.w;
        Bs[ac + 0][ar] = wv.x; Bs[ac + 1][ar] = wv.y;
        Bs[ac + 2][ar] = wv.z; Bs[ac + 3][ar] = wv.w;
        __syncthreads();
        #pragma unroll
        for (int k = 0; k < 8; k++) {
            float a[8], b[8];
            *(float4*)&a[0] = *(const float4*)&As[k][ty * 8];
            *(float4*)&a[4] = *(const float4*)&As[k][ty * 8 + 4];
            *(float4*)&b[0] = *(const float4*)&Bs[k][tx * 8];
            *(float4*)&b[4] = *(const float4*)&Bs[k][tx * 8 + 4];
            #pragma unroll
            for (int i = 0; i < 8; i++)
                #pragma unroll
                for (int j = 0; j < 8; j++)
                    acc[i][j] = fmaf(a[i], b[j], acc[i][j]);
        }
        __syncthreads();
    }

    float bv[8];
    #pragma unroll
    for (int j = 0; j < 8; j++)
        bv[j] = ADD_BIAS ? bias[n0 + tx * 8 + j] : 0.0f;

    #pragma unroll
    for (int i = 0; i < 8; i++) {
        int m = m0 + ty * 8 + i;
        if (m < M) {
            float* cp = C + (size_t)m * K + n0 + tx * 8;
            float4 v0 = make_float4(acc[i][0] + bv[0], acc[i][1] + bv[1],
                                    acc[i][2] + bv[2], acc[i][3] + bv[3]);
            float4 v1 = make_float4(acc[i][4] + bv[4], acc[i][5] + bv[5],
                                    acc[i][6] + bv[6], acc[i][7] + bv[7]);
            *(float4*)(cp + 0) = v0;
            *(float4*)(cp + 4) = v1;
        }
    }
}

// ---------------- degree + dinv --------------------------------------------
__global__ void k_deg(const int* __restrict__ dst) {
    int e = blockIdx.x * blockDim.x + threadIdx.x;
    if (e < N_EDGES) atomicAdd(&g_deg[dst[e]], 1.0f);
}

__global__ void k_dinv(void) {
    int i = blockIdx.x * blockDim.x + threadIdx.x;
    if (i < N_SPOTS) {
        float d = g_deg[i];
        g_dinv[i] = (d > 0.0f) ? (1.0f / sqrtf(d)) : 0.0f;
    }
}

// ---------------- msg init: msg[n,g] = bc[g] --------------------------------
__global__ void k_init_msg(float* __restrict__ msg, const float* __restrict__ bc) {
    size_t i = (size_t)blockIdx.x * blockDim.x + threadIdx.x;
    if (i < (size_t)N_SPOTS * N_GENES) msg[i] = bc[i & (N_GENES - 1)];
}

// ---------------- edge scatter: msg[dst] += norm * x[src] -------------------
// one block (128 threads) per edge; each thread handles 4 consecutive floats.
__global__ void k_scatter(const int* __restrict__ src, const int* __restrict__ dst,
                          float* __restrict__ msg) {
    int e = blockIdx.x;
    int s = src[e], d = dst[e];
    float nrm = g_dinv[s] * g_dinv[d];
    if (nrm == 0.0f) return;
    const float4* xs = (const float4*)(g_x + (size_t)s * N_GENES);
    float* md = msg + (size_t)d * N_GENES;
    int t = threadIdx.x;           // 0..127
    float4 v = xs[t];
    atomicAdd(md + 4 * t + 0, nrm * v.x);
    atomicAdd(md + 4 * t + 1, nrm * v.y);
    atomicAdd(md + 4 * t + 2, nrm * v.z);
    atomicAdd(md + 4 * t + 3, nrm * v.w);
}

// ---------------- column sums of gex (for the mean) -------------------------
__global__ void k_colsum(void) {
    __shared__ float s[N_GENES];
    int t = threadIdx.x;           // 256 threads
    s[t] = 0.0f; s[t + 256] = 0.0f;
    __syncthreads();
    for (int r = blockIdx.x; r < N_SPOTS; r += gridDim.x) {
        const float* row = g_gex + (size_t)r * N_GENES;
        s[t]       += row[t];
        s[t + 256] += row[t + 256];
    }
    __syncthreads();
    atomicAdd(&g_colsum[t], s[t]);
    atomicAdd(&g_colsum[t + 256], s[t + 256]);
}

// ---------------- mean-field scalar ----------------------------------------
__global__ void k_finalize(const float* __restrict__ Wc, const float* __restrict__ Wl,
                           float* __restrict__ out_scalar) {
    __shared__ float mean[N_GENES];
    __shared__ float red[N_GENES];
    int t = threadIdx.x;   // 512 threads
    mean[t] = g_colsum[t] * (1.0f / (float)N_SPOTS);
    __syncthreads();

    float v = 0.0f, u = 0.0f;
    const float* wc = Wc + (size_t)t * N_GENES;
    const float* wl = Wl + (size_t)t * N_GENES;
    for (int k = 0; k < N_GENES; k++) {
        float m = mean[k];
        v = fmaf((float)N_NEI * wc[k] + 2.0f * wl[k], m, v);   // (6Wc+2Wl)@mean
        u = fmaf(wl[k] + 0.5f * (float)N_NEI * wc[k], m, u);   // (Wl+3Wc)@mean
    }

    // g = || v ||
    red[t] = v * v;
    __syncthreads();
    for (int s = 256; s > 0; s >>= 1) {
        if (t < s) red[t] += red[t + s];
        __syncthreads();
    }
    float g2 = red[0];
    __syncthreads();

    // q = mean^T u
    red[t] = mean[t] * u;
    __syncthreads();
    for (int s = 256; s > 0; s >>= 1) {
        if (t < s) red[t] += red[t + s];
        __syncthreads();
    }
    if (t == 0) {
        float g = sqrtf(g2);
        float z_mean = -(float)N_SPOTS * red[0];
        float gc = fminf(g, 20.0f);
        float z_int;
        if (g > 20.0f)
            z_int = (float)N_SPOTS * (g - logf(g));
        else
            z_int = (float)N_SPOTS * logf((expf(gc) - expf(-gc)) / gc);
        out_scalar[0] = z_mean + z_int;
    }
}

// ---------------- launch ----------------------------------------------------
extern "C" void kernel_launch(void* const* d_in, const int* in_sizes, int n_in,
                              void* d_out, int out_size) {
    const float* sphex = (const float*)d_in[0];   // [100000, 511]
    const float* Wc    = (const float*)d_in[1];   // [512, 512]
    const float* bc    = (const float*)d_in[2];   // [512]
    const float* Wl    = (const float*)d_in[3];   // [512, 512]
    const float* bl    = (const float*)d_in[4];   // [512]
    const int*   eidx  = (const int*)d_in[5];     // [2, 600000]
    (void)in_sizes; (void)n_in; (void)out_size;

    const int* e_src = eidx;
    const int* e_dst = eidx + N_EDGES;

    float* out       = (float*)d_out;
    float* out_msg   = out;                                  // [N, G]
    float* out_intra = out + (size_t)N_SPOTS * N_GENES;      // [N, G]
    float* out_logz  = out + 2 * (size_t)N_SPOTS * N_GENES;  // [1]

    float *p_gex, *p_x;
    cudaGetSymbolAddress((void**)&p_gex, g_gex);
    cudaGetSymbolAddress((void**)&p_x,   g_x);

    // 0) zero accumulators
    k_zero<<<(N_SPOTS + 255) / 256, 256>>>();

    // 1) gex (warp per row)
    {
        int warps = N_SPOTS;
        int blocks = (warps * 32 + 255) / 256;
        k_gex<<<blocks, 256>>>(sphex);
    }

    // 2) GEMMs
    {
        dim3 grid(N_GENES / 128, (N_SPOTS + 127) / 128);
        k_sgemm512<false><<<grid, 256>>>(p_gex, Wc, nullptr, p_x, N_SPOTS);
        k_sgemm512<true ><<<grid, 256>>>(p_gex, Wl, bl, out_intra, N_SPOTS);
    }

    // 3) degrees + norms
    k_deg<<<(N_EDGES + 255) / 256, 256>>>(e_dst);
    k_dinv<<<(N_SPOTS + 255) / 256, 256>>>();

    // 4) msg = bc (broadcast init), then scatter-add edges
    {
        size_t total = (size_t)N_SPOTS * N_GENES;
        k_init_msg<<<(unsigned)((total + 255) / 256), 256>>>(out_msg, bc);
        k_scatter<<<N_EDGES, 128>>>(e_src, e_dst, out_msg);
    }

    // 5) column sums -> mean -> scalar
    k_colsum<<<512, 256>>>();
    k_finalize<<<1, 512>>>(Wc, Wl, out_logz);
}

// round 3
// speedup vs baseline: 2.1440x; 2.1440x over previous
#include <cuda_runtime.h>
#include <cuda_bf16.h>
#include <math.h>
#include <stdint.h>

// Problem constants (fixed by the dataset)
#define N_SPOTS   100000
#define N_GENES   512
#define N_SPH     511          // N_GENES - 1
#define N_EDGES   600000
#define N_NEI     6

// ---------------- scratch (device globals: no allocation allowed) ----------
__device__ float g_gex[(size_t)N_SPOTS * N_GENES];   // 204.8 MB
__device__ float g_x  [(size_t)N_SPOTS * N_GENES];   // 204.8 MB  (gex @ Wc^T)
__device__ float g_deg [N_SPOTS];
__device__ float g_dinv[N_SPOTS];
__device__ float g_colsum[N_GENES];

// ---------------- init: zero deg + colsum ----------------------------------
__global__ void k_zero(void) {
    int i = blockIdx.x * blockDim.x + threadIdx.x;
    if (i < N_SPOTS) g_deg[i] = 0.0f;
    if (i < N_GENES) g_colsum[i] = 0.0f;
}

// ---------------- gex: warp-per-row product scan ----------------------------
__global__ void k_gex(const float* __restrict__ sphex) {
    int gwarp = (blockIdx.x * blockDim.x + threadIdx.x) >> 5;
    int lane  = threadIdx.x & 31;
    if (gwarp >= N_SPOTS) return;
    const float* row = sphex + (size_t)gwarp * N_SPH;
    float* orow = g_gex + (size_t)gwarp * N_GENES;

    float P = 1.0f;
    for (int base = 0; base < N_SPH; base += 32) {
        int idx = base + lane;
        float s = 1.0f, c = 1.0f;
        if (idx < N_SPH) {
            float xv = row[idx];
            sincosf(xv, &s, &c);
        }
        float incl = s;
        #pragma unroll
        for (int off = 1; off < 32; off <<= 1) {
            float o = __shfl_up_sync(0xffffffffu, incl, off);
            if (lane >= off) incl *= o;
        }
        float excl = __shfl_up_sync(0xffffffffu, incl, 1);
        if (lane == 0) excl = 1.0f;
        if (idx < N_SPH) orow[idx] = P * excl * c;
        P *= __shfl_sync(0xffffffffu, incl, 31);
    }
    if (lane == 0) orow[N_SPH] = P;
}

// ---------------- TF32 tensor-core GEMM ------------------------------------
// C[m,o] = sum_k A[m,k] * W[o,k] (+ bias[o])
// A: M x 512 row-major, W: 512 x 512 row-major ("B" is k-major per output col
// = mma .col layout). Block tile 128x128x32, 8 warps, warp tile 64x32.
#define BK 32
#define KPAD 4          // smem row stride 36 floats -> conflict-free frag loads

__device__ __forceinline__ float to_tf32(float x) {
    float r;
    asm("cvt.rna.tf32.f32 %0, %1;" : "=f"(r) : "f"(x));
    return r;
}

__device__ __forceinline__ void mma_tf32(float* c, const float* a, const float* b) {
    const uint32_t* A = reinterpret_cast<const uint32_t*>(a);
    const uint32_t* B = reinterpret_cast<const uint32_t*>(b);
    asm volatile(
        "mma.sync.aligned.m16n8k8.row.col.f32.tf32.tf32.f32 "
        "{%0,%1,%2,%3}, {%4,%5,%6,%7}, {%8,%9}, {%0,%1,%2,%3};"
        : "+f"(c[0]), "+f"(c[1]), "+f"(c[2]), "+f"(c[3])
        : "r"(A[0]), "r"(A[1]), "r"(A[2]), "r"(A[3]), "r"(B[0]), "r"(B[1]));
}

template <bool ADD_BIAS>
__global__ void __launch_bounds__(256, 2)
k_mma_gemm(const float* __restrict__ A, const float* __restrict__ W,
           const float* __restrict__ bias, float* __restrict__ C, int M) {
    const int K = N_GENES;
    __shared__ float As[128][BK + KPAD];
    __shared__ float Bs[128][BK + KPAD];

    int tid  = threadIdx.x;
    int warp = tid >> 5;
    int lane = tid & 31;
    int wm = warp >> 2;          // 0..1  -> rows warp tile (64)
    int wn = warp & 3;           // 0..3  -> cols warp tile (32)
    int n0 = blockIdx.x * 128;
    int m0 = blockIdx.y * 128;

    int gq = lane >> 2;          // 0..7
    int gr = lane & 3;           // 0..3

    float acc[4][4][4];
    #pragma unroll
    for (int i = 0; i < 4; i++)
        #pragma unroll
        for (int j = 0; j < 4; j++)
            #pragma unroll
            for (int r = 0; r < 4; r++) acc[i][j][r] = 0.0f;

    for (int kt = 0; kt < K; kt += BK) {
        // load A tile (128 x 32) and W tile (128 x 32), converting to tf32
        #pragma unroll
        for (int j = 0; j < 4; j++) {
            int i = tid + 256 * j;             // 0..1023 float4 slots
            int row = i >> 3;
            int c4  = (i & 7) * 4;
            int m = m0 + row;
            float4 av = (m < M) ? *(const float4*)(A + (size_t)m * K + kt + c4)
                                : make_float4(0.f, 0.f, 0.f, 0.f);
            float4 wv = *(const float4*)(W + (size_t)(n0 + row) * K + kt + c4);
            av.x = to_tf32(av.x); av.y = to_tf32(av.y);
            av.z = to_tf32(av.z); av.w = to_tf32(av.w);
            wv.x = to_tf32(wv.x); wv.y = to_tf32(wv.y);
            wv.z = to_tf32(wv.z); wv.w = to_tf32(wv.w);
            *(float4*)&As[row][c4] = av;
            *(float4*)&Bs[row][c4] = wv;
        }
        __syncthreads();

        #pragma unroll
        for (int s = 0; s < 4; s++) {
            int k0 = s * 8 + gr;
            int k1 = k0 + 4;
            float af[4][4], bf[4][2];
            #pragma unroll
            for (int mf = 0; mf < 4; mf++) {
                int r0 = wm * 64 + mf * 16 + gq;
                af[mf][0] = As[r0][k0];
                af[mf][1] = As[r0 + 8][k0];
                af[mf][2] = As[r0][k1];
                af[mf][3] = As[r0 + 8][k1];
            }
            #pragma unroll
            for (int nf = 0; nf < 4; nf++) {
                int cN = wn * 32 + nf * 8 + gq;
                bf[nf][0] = Bs[cN][k0];
                bf[nf][1] = Bs[cN][k1];
            }
            #pragma unroll
            for (int mf = 0; mf < 4; mf++)
                #pragma unroll
                for (int nf = 0; nf < 4; nf++)
                    mma_tf32(acc[mf][nf], af[mf], bf[nf]);
        }
        __syncthreads();
    }

    // epilogue
    #pragma unroll
    for (int mf = 0; mf < 4; mf++) {
        int r0 = m0 + wm * 64 + mf * 16 + gq;
        #pragma unroll
        for (int nf = 0; nf < 4; nf++) {
            int cN = n0 + wn * 32 + nf * 8 + gr * 2;
            float b0 = ADD_BIAS ? bias[cN]     : 0.0f;
            float b1 = ADD_BIAS ? bias[cN + 1] : 0.0f;
            if (r0 < M) {
                float2 v = make_float2(acc[mf][nf][0] + b0, acc[mf][nf][1] + b1);
                *(float2*)(C + (size_t)r0 * K + cN) = v;
            }
            if (r0 + 8 < M) {
                float2 v = make_float2(acc[mf][nf][2] + b0, acc[mf][nf][3] + b1);
                *(float2*)(C + (size_t)(r0 + 8) * K + cN) = v;
            }
        }
    }
}

// ---------------- degree + dinv --------------------------------------------
__global__ void k_deg(const int* __restrict__ dst) {
    int e = blockIdx.x * blockDim.x + threadIdx.x;
    if (e < N_EDGES) atomicAdd(&g_deg[dst[e]], 1.0f);
}

__global__ void k_dinv(void) {
    int i = blockIdx.x * blockDim.x + threadIdx.x;
    if (i < N_SPOTS) {
        float d = g_deg[i];
        g_dinv[i] = (d > 0.0f) ? (1.0f / sqrtf(d)) : 0.0f;
    }
}

// ---------------- msg init: msg[n,g] = bc[g] --------------------------------
__global__ void k_init_msg(float* __restrict__ msg, const float* __restrict__ bc) {
    size_t i = (size_t)blockIdx.x * blockDim.x + threadIdx.x;
    if (i < (size_t)N_SPOTS * N_GENES) msg[i] = bc[i & (N_GENES - 1)];
}

// ---------------- edge scatter: msg[dst] += norm * x[src] -------------------
// one block (128 threads) per edge; one red.global.add.v4 per thread.
__global__ void k_scatter(const int* __restrict__ src, const int* __restrict__ dst,
                          float* __restrict__ msg) {
    int e = blockIdx.x;
    int s = src[e], d = dst[e];
    float nrm = g_dinv[s] * g_dinv[d];
    if (nrm == 0.0f) return;
    const float4* xs = (const float4*)(g_x + (size_t)s * N_GENES);
    float* md = msg + (size_t)d * N_GENES;
    int t = threadIdx.x;           // 0..127
    float4 v = xs[t];
    asm volatile("red.global.add.v4.f32 [%0], {%1,%2,%3,%4};"
                 :: "l"(md + 4 * t), "f"(nrm * v.x), "f"(nrm * v.y),
                    "f"(nrm * v.z), "f"(nrm * v.w)
                 : "memory");
}

// ---------------- column sums of gex (for the mean) -------------------------
__global__ void k_colsum(void) {
    __shared__ float s[N_GENES];
    int t = threadIdx.x;           // 256 threads
    s[t] = 0.0f; s[t + 256] = 0.0f;
    __syncthreads();
    for (int r = blockIdx.x; r < N_SPOTS; r += gridDim.x) {
        const float* row = g_gex + (size_t)r * N_GENES;
        s[t]       += row[t];
        s[t + 256] += row[t + 256];
    }
    __syncthreads();
    atomicAdd(&g_colsum[t], s[t]);
    atomicAdd(&g_colsum[t + 256], s[t + 256]);
}

// ---------------- mean-field scalar ----------------------------------------
__global__ void k_finalize(const float* __restrict__ Wc, const float* __restrict__ Wl,
                           float* __restrict__ out_scalar) {
    __shared__ float mean[N_GENES];
    __shared__ float red[N_GENES];
    int t = threadIdx.x;   // 512 threads
    mean[t] = g_colsum[t] * (1.0f / (float)N_SPOTS);
    __syncthreads();

    float v = 0.0f, u = 0.0f;
    const float* wc = Wc + (size_t)t * N_GENES;
    const float* wl = Wl + (size_t)t * N_GENES;
    for (int k = 0; k < N_GENES; k++) {
        float m = mean[k];
        v = fmaf((float)N_NEI * wc[k] + 2.0f * wl[k], m, v);
        u = fmaf(wl[k] + 0.5f * (float)N_NEI * wc[k], m, u);
    }

    red[t] = v * v;
    __syncthreads();
    for (int s = 256; s > 0; s >>= 1) {
        if (t < s) red[t] += red[t + s];
        __syncthreads();
    }
    float g2 = red[0];
    __syncthreads();

    red[t] = mean[t] * u;
    __syncthreads();
    for (int s = 256; s > 0; s >>= 1) {
        if (t < s) red[t] += red[t + s];
        __syncthreads();
    }
    if (t == 0) {
        float g = sqrtf(g2);
        float z_mean = -(float)N_SPOTS * red[0];
        float gc = fminf(g, 20.0f);
        float z_int;
        if (g > 20.0f)
            z_int = (float)N_SPOTS * (g - logf(g));
        else
            z_int = (float)N_SPOTS * logf((expf(gc) - expf(-gc)) / gc);
        out_scalar[0] = z_mean + z_int;
    }
}

// ---------------- launch ----------------------------------------------------
extern "C" void kernel_launch(void* const* d_in, const int* in_sizes, int n_in,
                              void* d_out, int out_size) {
    const float* sphex = (const float*)d_in[0];   // [100000, 511]
    const float* Wc    = (const float*)d_in[1];   // [512, 512]
    const float* bc    = (const float*)d_in[2];   // [512]
    const float* Wl    = (const float*)d_in[3];   // [512, 512]
    const float* bl    = (const float*)d_in[4];   // [512]
    const int*   eidx  = (const int*)d_in[5];     // [2, 600000]
    (void)in_sizes; (void)n_in; (void)out_size;

    const int* e_src = eidx;
    const int* e_dst = eidx + N_EDGES;

    float* out       = (float*)d_out;
    float* out_msg   = out;                                  // [N, G]
    float* out_intra = out + (size_t)N_SPOTS * N_GENES;      // [N, G]
    float* out_logz  = out + 2 * (size_t)N_SPOTS * N_GENES;  // [1]

    float *p_gex, *p_x;
    cudaGetSymbolAddress((void**)&p_gex, g_gex);
    cudaGetSymbolAddress((void**)&p_x,   g_x);

    // 0) zero accumulators
    k_zero<<<(N_SPOTS + 255) / 256, 256>>>();

    // 1) gex (warp per row)
    {
        int warps = N_SPOTS;
        int blocks = (warps * 32 + 255) / 256;
        k_gex<<<blocks, 256>>>(sphex);
    }

    // 2) GEMMs (tf32 tensor cores)
    {
        dim3 grid(N_GENES / 128, (N_SPOTS + 127) / 128);
        k_mma_gemm<false><<<grid, 256>>>(p_gex, Wc, nullptr, p_x, N_SPOTS);
        k_mma_gemm<true ><<<grid, 256>>>(p_gex, Wl, bl, out_intra, N_SPOTS);
    }

    // 3) degrees + norms
    k_deg<<<(N_EDGES + 255) / 256, 256>>>(e_dst);
    k_dinv<<<(N_SPOTS + 255) / 256, 256>>>();

    // 4) msg = bc (broadcast init), then scatter-add edges
    {
        size_t total = (size_t)N_SPOTS * N_GENES;
        k_init_msg<<<(unsigned)((total + 255) / 256), 256>>>(out_msg, bc);
        k_scatter<<<N_EDGES, 128>>>(e_src, e_dst, out_msg);
    }

    // 5) column sums -> mean -> scalar
    k_colsum<<<512, 256>>>();
    k_finalize<<<1, 512>>>(Wc, Wl, out_logz);
}